// round 15
// baseline (speedup 1.0000x reference)
#include <cuda_runtime.h>
#include <cuda_fp16.h>
#include <cstdint>
#include <math.h>

#define DET 512
#define NTH 180
#define B   4
#define OUT 362
#define RAD 181          // OUT//2 per reference
#define PI_F 3.14159265358979323846f

#define PSTG   3         // cp.async ring PAIR stages (2 angles each)
#define NSPLIT 6         // angle splits: 6 x 30 -> 864 blocks (one wave @6/SM)
#define APB    30        // angles per block (even)
#define WIN    64        // staged detector window (dets)
#define WROW   68        // window dets incl 4 zero slots
#define ZSLOT  64        // zero det slot
#define GATE_U 0x43FF8000u   // bits of 511.0f

// half4-interleaved projections [a][det][b], 256-half pads both ends
__device__ __align__(16) __half g_fh[256 + NTH * DET * 4 + 256];

// ---------------------------------------------------------------------------
// Kernel 1 (FUSED): ramp filter + pack + zero-out.
// One block per angle, 512 threads = 4 warpgroups (one batch each).
//   out[k] = 0.5 x[k] + sum_{d odd} g(d) x[k-d],  g(d) = -2/(pi d)^2
// parity-compressed: even/odd outputs correlate with the opposite-parity
// half-signal against T[j] = g(|2j-513|). Both T and x windows prefetched
// one iteration ahead. Results staged in smem, packed to half4 [a][det][b].
// Each block also zeroes its slice of the output buffer.
// ---------------------------------------------------------------------------
__global__ void __launch_bounds__(512) filter_pack_kernel(
    const float* __restrict__ x, float* __restrict__ out)
{
    __shared__ __align__(16) float xe[B][260];   // +4 pad for xb prefetch
    __shared__ __align__(16) float xo[B][260];
    __shared__ __align__(16) float Tbuf[4 + 512 + 4];
    __shared__ __align__(16) float res[B][DET];

    float* T = Tbuf + 4;

    const int a   = blockIdx.x;
    const int tid = threadIdx.x;
    const int b   = tid >> 7;            // warpgroup = batch
    const int wt  = tid & 127;

    {
        int m0 = 4 * wt;
        const float* xp = x + (b * DET + m0) * NTH + a;
        float v0 = xp[0 * NTH], v1 = xp[1 * NTH];
        float v2 = xp[2 * NTH], v3 = xp[3 * NTH];
        xe[b][m0 / 2]     = v0;  xo[b][m0 / 2]     = v1;
        xe[b][m0 / 2 + 1] = v2;  xo[b][m0 / 2 + 1] = v3;
    }
    if (tid < 512) {
        int d = 2 * tid - 513; if (d < 0) d = -d;
        float fd = (float)d;
        T[tid] = -2.0f / (PI_F * PI_F * fd * fd);
    }
    if (tid < 4) { Tbuf[tid] = 0.0f; Tbuf[516 + tid] = 0.0f; }
    __syncthreads();

    const int odd = wt >> 6;
    const int t   = wt & 63;
    const int K0  = 4 * t;
    const float* xop = odd ? xe[b] : xo[b];   // opposite-parity source

    float acc0 = 0.f, acc1 = 0.f, acc2 = 0.f, acc3 = 0.f;

    if (!odd) {
        int j0 = K0 + 256;
        float4 tb = *reinterpret_cast<const float4*>(T + j0);
        float4 ta = *reinterpret_cast<const float4*>(T + j0 - 4);
        float4 xb = *reinterpret_cast<const float4*>(xop);
        #pragma unroll 4
        for (int M0 = 0; M0 < 256; M0 += 4, j0 -= 4) {
            float4 tn = *reinterpret_cast<const float4*>(T + j0 - 8);
            float4 xn = *reinterpret_cast<const float4*>(xop + M0 + 4);
            acc0 = fmaf(tb.x, xb.x, acc0); acc0 = fmaf(ta.w, xb.y, acc0);
            acc0 = fmaf(ta.z, xb.z, acc0); acc0 = fmaf(ta.y, xb.w, acc0);
            acc1 = fmaf(tb.y, xb.x, acc1); acc1 = fmaf(tb.x, xb.y, acc1);
            acc1 = fmaf(ta.w, xb.z, acc1); acc1 = fmaf(ta.z, xb.w, acc1);
            acc2 = fmaf(tb.z, xb.x, acc2); acc2 = fmaf(tb.y, xb.y, acc2);
            acc2 = fmaf(tb.x, xb.z, acc2); acc2 = fmaf(ta.w, xb.w, acc2);
            acc3 = fmaf(tb.w, xb.x, acc3); acc3 = fmaf(tb.z, xb.y, acc3);
            acc3 = fmaf(tb.y, xb.z, acc3); acc3 = fmaf(tb.x, xb.w, acc3);
            tb = ta; ta = tn; xb = xn;
        }
        float4 xc = *reinterpret_cast<const float4*>(xe[b] + K0);
        acc0 = fmaf(0.5f, xc.x, acc0);
        acc1 = fmaf(0.5f, xc.y, acc1);
        acc2 = fmaf(0.5f, xc.z, acc2);
        acc3 = fmaf(0.5f, xc.w, acc3);
    } else {
        int j0 = 256 - K0;
        float4 ta = *reinterpret_cast<const float4*>(T + j0 - 4);
        float4 tb = *reinterpret_cast<const float4*>(T + j0);
        float4 xb = *reinterpret_cast<const float4*>(xop);
        #pragma unroll 4
        for (int M0 = 0; M0 < 256; M0 += 4, j0 += 4) {
            float4 tn = *reinterpret_cast<const float4*>(T + j0 + 4);
            float4 xn = *reinterpret_cast<const float4*>(xop + M0 + 4);
            acc0 = fmaf(tb.x, xb.x, acc0); acc0 = fmaf(tb.y, xb.y, acc0);
            acc0 = fmaf(tb.z, xb.z, acc0); acc0 = fmaf(tb.w, xb.w, acc0);
            acc1 = fmaf(ta.w, xb.x, acc1); acc1 = fmaf(tb.x, xb.y, acc1);
            acc1 = fmaf(tb.y, xb.z, acc1); acc1 = fmaf(tb.z, xb.w, acc1);
            acc2 = fmaf(ta.z, xb.x, acc2); acc2 = fmaf(ta.w, xb.y, acc2);
            acc2 = fmaf(tb.x, xb.z, acc2); acc2 = fmaf(tb.y, xb.w, acc2);
            acc3 = fmaf(ta.y, xb.x, acc3); acc3 = fmaf(ta.z, xb.y, acc3);
            acc3 = fmaf(ta.w, xb.z, acc3); acc3 = fmaf(tb.x, xb.w, acc3);
            ta = tb; tb = tn; xb = xn;
        }
        float4 xc = *reinterpret_cast<const float4*>(xo[b] + K0);
        acc0 = fmaf(0.5f, xc.x, acc0);
        acc1 = fmaf(0.5f, xc.y, acc1);
        acc2 = fmaf(0.5f, xc.z, acc2);
        acc3 = fmaf(0.5f, xc.w, acc3);
    }

    // stage results: dets 8t+odd+{0,2,4,6} of batch b
    {
        float* o = res[b] + 8 * t + odd;
        o[0] = acc0; o[2] = acc1; o[4] = acc2; o[6] = acc3;
    }
    __syncthreads();

    // pack: thread d packs det d (all 4 batches) -> uint2
    {
        int d = tid;
        __half2 h01 = __floats2half2_rn(res[0][d], res[1][d]);
        __half2 h23 = __floats2half2_rn(res[2][d], res[3][d]);
        uint2 pk;
        pk.x = *reinterpret_cast<unsigned int*>(&h01);
        pk.y = *reinterpret_cast<unsigned int*>(&h23);
        *reinterpret_cast<uint2*>(g_fh + 256 + (a * DET + d) * 4) = pk;
    }

    // zero the output slice (independent of pack)
    {
        const int n4 = (B * OUT * OUT) / 4;      // 131044
        for (int i = blockIdx.x * 512 + tid; i < n4; i += NTH * 512)
            reinterpret_cast<float4*>(out)[i] = make_float4(0.f, 0.f, 0.f, 0.f);
    }
}

// ---------------------------------------------------------------------------
// Kernel 2: backprojection (R12 version), angle-split 6 ways (30 each), fp16
// windowed PAIR staging (one barrier per 2 angles), uint gate, half lerp,
// fp32 accum, RED.ADD into out.
// pos = (j-RAD)*cos(th) - (i-RAD)*sin(th) + DET/2
// ---------------------------------------------------------------------------
__global__ void __launch_bounds__(256, 6) backproj_kernel(float* __restrict__ out)
{
    __shared__ __align__(16) __half win[PSTG][2][WROW * 4]; // 3264 B
    __shared__ float cs[APB];
    __shared__ float sn[APB];
    __shared__ int   w0s[APB];

    const int z  = blockIdx.z;
    const int a0 = z * APB;
    const int j0 = blockIdx.x * 32;
    const int i0 = blockIdx.y * 32;
    const int tid = threadIdx.x;
    const int tx = tid & 31;
    const int ty = tid >> 5;             // 0..7

    if (tid < APB) {
        float ang = (float)(a0 + tid) * (PI_F / 180.0f);
        float c = cosf(ang);
        float s = sinf(ang);
        cs[tid] = c;
        sn[tid] = s;
        // min over tile of pos = jf*c - xf*s + 256   (s >= 0 on [0,pi))
        float jlo = (float)(j0 - RAD), jhi = (float)(j0 + 31 - RAD);
        float xhi = (float)(i0 + 31 - RAD);
        float minpos = (c >= 0.0f ? c * jlo : c * jhi) - s * xhi + 256.0f;
        int w0 = (int)floorf(minpos) - 1;
        w0s[tid] = (w0 >> 2) << 2;       // align down to multiple of 4
    }
    // zero det slots 64..67 (uints 128..135) of all PSTG*2 windows
    if (tid < PSTG * 2 * 8) {
        int p = tid & 7;
        int w = tid >> 3;                // 0..5
        unsigned int* wu = reinterpret_cast<unsigned int*>(&win[0][0][0]);
        wu[w * (WROW * 4 / 2) + 128 + p] = 0u;
    }
    __syncthreads();   // w0s needed by staging below

    // staging: threads 0..63 copy 16B each; hw = angle-in-pair, sch = chunk
    const int hw  = (tid >> 5) & 1;
    const int sch = tid & 31;
    const __half* fb = g_fh + 256;
    unsigned int sdst[PSTG];
    #pragma unroll
    for (int st = 0; st < PSTG; st++) {
        unsigned int u;
        asm("{ .reg .u64 t; cvta.to.shared.u64 t, %1; cvt.u32.u64 %0, t; }"
            : "=r"(u) : "l"((const void*)&win[st][hw][sch * 8]));
        sdst[st] = u;
    }

    // prologue: prefetch pairs 0 and 1 into stages 0 and 1
    if (tid < 64) {
        #pragma unroll
        for (int p = 0; p < 2; p++) {
            int q = 2 * p + hw;
            const __half* src = fb + ((a0 + q) * DET + w0s[q]) * 4 + sch * 8;
            asm volatile("cp.async.ca.shared.global [%0], [%1], 16;\n"
                         :: "r"(sdst[p]), "l"(src) : "memory");
        }
    }
    asm volatile("cp.async.commit_group;\n" ::: "memory");
    asm volatile("cp.async.commit_group;\n" ::: "memory");

    const float jf = (float)(j0 + tx - RAD);
    float xpr[4];
    #pragma unroll
    for (int r = 0; r < 4; r++) xpr[r] = (float)(i0 + ty + 8 * r - RAD);

    float acc[B][4];
    #pragma unroll
    for (int bb = 0; bb < B; bb++)
        #pragma unroll
        for (int r = 0; r < 4; r++) acc[bb][r] = 0.0f;

    const int npairs = APB / 2;          // 15
    int st = 0;
    for (int p = 0; p < npairs; p++) {
        if (p < npairs - 1) {
            asm volatile("cp.async.wait_group 1;\n" ::: "memory");
        } else {
            asm volatile("cp.async.wait_group 0;\n" ::: "memory");
        }
        __syncthreads();   // pair p staged & visible; stage (st+2)%3 free

        {
            int nst = st + 2; if (nst >= PSTG) nst -= PSTG;
            if (p + 2 < npairs && tid < 64) {
                int q = 2 * (p + 2) + hw;
                const __half* src = fb + ((a0 + q) * DET + w0s[q]) * 4
                                  + sch * 8;
                asm volatile("cp.async.ca.shared.global [%0], [%1], 16;\n"
                             :: "r"(sdst[nst]), "l"(src) : "memory");
            }
            asm volatile("cp.async.commit_group;\n" ::: "memory");
        }

        #pragma unroll
        for (int h = 0; h < 2; h++) {
            const int q = 2 * p + h;
            const float c = cs[q];
            const float s = sn[q];
            const int   w0a = w0s[q];
            const float base = fmaf(jf, c, (float)(DET / 2));
            const __half* wp = win[st][h];

            #pragma unroll
            for (int r = 0; r < 4; r++) {
                float pos = fmaf(-xpr[r], s, base);
                int   idx = __float2int_rd(pos);
                float w   = pos - (float)idx;
                // gate: pos in [0,511] <=> float bits <= bits(511.0f)
                int sel = (__float_as_uint(pos) <= GATE_U) ? (idx - w0a)
                                                           : ZSLOT;
                uint2 qa = *reinterpret_cast<const uint2*>(wp + sel * 4);
                uint2 qb = *reinterpret_cast<const uint2*>(wp + sel * 4 + 4);
                __half2 w2 = __float2half2_rn(w);
                __half2 qa01 = *reinterpret_cast<__half2*>(&qa.x);
                __half2 qa23 = *reinterpret_cast<__half2*>(&qa.y);
                __half2 qb01 = *reinterpret_cast<__half2*>(&qb.x);
                __half2 qb23 = *reinterpret_cast<__half2*>(&qb.y);
                __half2 v01 = __hfma2(w2, __hsub2(qb01, qa01), qa01);
                __half2 v23 = __hfma2(w2, __hsub2(qb23, qa23), qa23);
                float2 f01 = __half22float2(v01);
                float2 f23 = __half22float2(v23);
                acc[0][r] += f01.x;
                acc[1][r] += f01.y;
                acc[2][r] += f23.x;
                acc[3][r] += f23.y;
            }
        }

        st++; if (st >= PSTG) st -= PSTG;
    }

    const float scale = PI_F / (2.0f * (float)NTH);
    const int j = j0 + tx;
    if (j < OUT) {
        #pragma unroll
        for (int bb = 0; bb < B; bb++) {
            #pragma unroll
            for (int r = 0; r < 4; r++) {
                int i = i0 + ty + 8 * r;
                if (i < OUT)
                    atomicAdd(&out[(bb * OUT + i) * OUT + j], acc[bb][r] * scale);
            }
        }
    }
}

extern "C" void kernel_launch(void* const* d_in, const int* in_sizes, int n_in,
                              void* d_out, int out_size)
{
    const float* x = (const float*)d_in[0];
    float* out = (float*)d_out;

    filter_pack_kernel<<<NTH, 512>>>(x, out);

    dim3 grid((OUT + 31) / 32, (OUT + 31) / 32, NSPLIT);   // 12 x 12 x 6
    backproj_kernel<<<grid, 256>>>(out);
}

// round 16
// speedup vs baseline: 1.1024x; 1.1024x over previous
#include <cuda_runtime.h>
#include <cuda_fp16.h>
#include <cstdint>
#include <math.h>

#define DET 512
#define NTH 180
#define B   4
#define OUT 362
#define RAD 181          // OUT//2 per reference
#define PI_F 3.14159265358979323846f

#define PSTG   3         // cp.async ring PAIR stages (2 angles each)
#define NSPLIT 6         // angle splits: 6 x 30 -> 864 blocks (one wave @6/SM)
#define APB    30        // angles per block (even)
#define WIN    64        // staged detector window (dets)
#define WROW   68        // window dets incl 4 zero slots
#define ZSLOT  64        // zero det slot
#define GATE_U 0x43FF8000u   // bits of 511.0f

// half4-interleaved projections [a][det][b], 256-half pads both ends
__device__ __align__(16) __half g_fh[256 + NTH * DET * 4 + 256];

// ---------------------------------------------------------------------------
// Kernel 1: ramp filter as two dense parity-compressed correlations,
// writing half4-interleaved g_fh DIRECTLY (scattered STG.16, no pack pass)
// and zeroing the output buffer.
//   out[k] = 0.5 x[k] + sum_{d odd} g(d) x[k-d],  g(d) = -2/(pi d)^2
// T[j] = g(|2j-513|); register-shifted T window + one-iteration prefetch.
// ---------------------------------------------------------------------------
__global__ void __launch_bounds__(128) filter_kernel(const float* __restrict__ x,
                                                     float* __restrict__ out)
{
    __shared__ __align__(16) float xe[256];
    __shared__ __align__(16) float xo[256];
    __shared__ __align__(16) float Tbuf[4 + 512 + 4];

    float* T = Tbuf + 4;

    const int a = blockIdx.x;
    const int b = blockIdx.y;
    const int tid = threadIdx.x;

    {
        int m0 = 4 * tid;
        const float* xp = x + (b * DET + m0) * NTH + a;
        float v0 = xp[0 * NTH], v1 = xp[1 * NTH];
        float v2 = xp[2 * NTH], v3 = xp[3 * NTH];
        xe[m0 / 2]     = v0;  xo[m0 / 2]     = v1;
        xe[m0 / 2 + 1] = v2;  xo[m0 / 2 + 1] = v3;
    }
    #pragma unroll
    for (int j = tid; j < 512; j += 128) {
        int d = 2 * j - 513; if (d < 0) d = -d;
        float fd = (float)d;
        T[j] = -2.0f / (PI_F * PI_F * fd * fd);
    }
    if (tid < 4) { Tbuf[tid] = 0.0f; Tbuf[516 + tid] = 0.0f; }

    // zero the output slice while waiting (independent of smem contents)
    {
        const int n4 = (B * OUT * OUT) / 4;      // 131044
        const int bid = blockIdx.y * NTH + blockIdx.x;
        for (int i = bid * 128 + tid; i < n4; i += NTH * B * 128)
            reinterpret_cast<float4*>(out)[i] = make_float4(0.f, 0.f, 0.f, 0.f);
    }
    __syncthreads();

    const int odd = tid >> 6;
    const int t   = tid & 63;
    const int K0  = 4 * t;

    float acc0 = 0.f, acc1 = 0.f, acc2 = 0.f, acc3 = 0.f;

    if (!odd) {
        int j0 = K0 + 256;
        float4 tb = *reinterpret_cast<const float4*>(T + j0);
        float4 ta = *reinterpret_cast<const float4*>(T + j0 - 4);
        #pragma unroll 4
        for (int M0 = 0; M0 < 256; M0 += 4, j0 -= 4) {
            float4 xb = *reinterpret_cast<const float4*>(xo + M0);
            float4 tn = *reinterpret_cast<const float4*>(T + j0 - 8);
            acc0 = fmaf(tb.x, xb.x, acc0); acc0 = fmaf(ta.w, xb.y, acc0);
            acc0 = fmaf(ta.z, xb.z, acc0); acc0 = fmaf(ta.y, xb.w, acc0);
            acc1 = fmaf(tb.y, xb.x, acc1); acc1 = fmaf(tb.x, xb.y, acc1);
            acc1 = fmaf(ta.w, xb.z, acc1); acc1 = fmaf(ta.z, xb.w, acc1);
            acc2 = fmaf(tb.z, xb.x, acc2); acc2 = fmaf(tb.y, xb.y, acc2);
            acc2 = fmaf(tb.x, xb.z, acc2); acc2 = fmaf(ta.w, xb.w, acc2);
            acc3 = fmaf(tb.w, xb.x, acc3); acc3 = fmaf(tb.z, xb.y, acc3);
            acc3 = fmaf(tb.y, xb.z, acc3); acc3 = fmaf(tb.x, xb.w, acc3);
            tb = ta; ta = tn;
        }
        float4 xc = *reinterpret_cast<const float4*>(xe + K0);
        acc0 = fmaf(0.5f, xc.x, acc0);
        acc1 = fmaf(0.5f, xc.y, acc1);
        acc2 = fmaf(0.5f, xc.z, acc2);
        acc3 = fmaf(0.5f, xc.w, acc3);
    } else {
        int j0 = 256 - K0;
        float4 ta = *reinterpret_cast<const float4*>(T + j0 - 4);
        float4 tb = *reinterpret_cast<const float4*>(T + j0);
        #pragma unroll 4
        for (int M0 = 0; M0 < 256; M0 += 4, j0 += 4) {
            float4 xb = *reinterpret_cast<const float4*>(xe + M0);
            float4 tn = *reinterpret_cast<const float4*>(T + j0 + 4);
            acc0 = fmaf(tb.x, xb.x, acc0); acc0 = fmaf(tb.y, xb.y, acc0);
            acc0 = fmaf(tb.z, xb.z, acc0); acc0 = fmaf(tb.w, xb.w, acc0);
            acc1 = fmaf(ta.w, xb.x, acc1); acc1 = fmaf(tb.x, xb.y, acc1);
            acc1 = fmaf(tb.y, xb.z, acc1); acc1 = fmaf(tb.z, xb.w, acc1);
            acc2 = fmaf(ta.z, xb.x, acc2); acc2 = fmaf(ta.w, xb.y, acc2);
            acc2 = fmaf(tb.x, xb.z, acc2); acc2 = fmaf(tb.y, xb.w, acc2);
            acc3 = fmaf(ta.y, xb.x, acc3); acc3 = fmaf(ta.z, xb.y, acc3);
            acc3 = fmaf(ta.w, xb.z, acc3); acc3 = fmaf(tb.x, xb.w, acc3);
            ta = tb; tb = tn;
        }
        float4 xc = *reinterpret_cast<const float4*>(xo + K0);
        acc0 = fmaf(0.5f, xc.x, acc0);
        acc1 = fmaf(0.5f, xc.y, acc1);
        acc2 = fmaf(0.5f, xc.z, acc2);
        acc3 = fmaf(0.5f, xc.w, acc3);
    }

    // direct interleaved store: dets 8t+odd+{0,2,4,6}, batch b
    {
        __half* gh = g_fh + 256 + (a * DET + 8 * t + odd) * 4 + b;
        gh[0 * 4] = __float2half(acc0);
        gh[2 * 4] = __float2half(acc1);
        gh[4 * 4] = __float2half(acc2);
        gh[6 * 4] = __float2half(acc3);
    }
}

// ---------------------------------------------------------------------------
// Kernel 2: backprojection (R12 version), angle-split 6 ways (30 each), fp16
// windowed PAIR staging (one barrier per 2 angles), uint gate, half lerp,
// fp32 accum, RED.ADD into out.
// pos = (j-RAD)*cos(th) - (i-RAD)*sin(th) + DET/2
// ---------------------------------------------------------------------------
__global__ void __launch_bounds__(256, 6) backproj_kernel(float* __restrict__ out)
{
    __shared__ __align__(16) __half win[PSTG][2][WROW * 4]; // 3264 B
    __shared__ float cs[APB];
    __shared__ float sn[APB];
    __shared__ int   w0s[APB];

    const int z  = blockIdx.z;
    const int a0 = z * APB;
    const int j0 = blockIdx.x * 32;
    const int i0 = blockIdx.y * 32;
    const int tid = threadIdx.x;
    const int tx = tid & 31;
    const int ty = tid >> 5;             // 0..7

    if (tid < APB) {
        float ang = (float)(a0 + tid) * (PI_F / 180.0f);
        float c = cosf(ang);
        float s = sinf(ang);
        cs[tid] = c;
        sn[tid] = s;
        // min over tile of pos = jf*c - xf*s + 256   (s >= 0 on [0,pi))
        float jlo = (float)(j0 - RAD), jhi = (float)(j0 + 31 - RAD);
        float xhi = (float)(i0 + 31 - RAD);
        float minpos = (c >= 0.0f ? c * jlo : c * jhi) - s * xhi + 256.0f;
        int w0 = (int)floorf(minpos) - 1;
        w0s[tid] = (w0 >> 2) << 2;       // align down to multiple of 4
    }
    // zero det slots 64..67 (uints 128..135) of all PSTG*2 windows
    if (tid < PSTG * 2 * 8) {
        int p = tid & 7;
        int w = tid >> 3;                // 0..5
        unsigned int* wu = reinterpret_cast<unsigned int*>(&win[0][0][0]);
        wu[w * (WROW * 4 / 2) + 128 + p] = 0u;
    }
    __syncthreads();   // w0s needed by staging below

    // staging: threads 0..63 copy 16B each; hw = angle-in-pair, sch = chunk
    const int hw  = (tid >> 5) & 1;
    const int sch = tid & 31;
    const __half* fb = g_fh + 256;
    unsigned int sdst[PSTG];
    #pragma unroll
    for (int st = 0; st < PSTG; st++) {
        unsigned int u;
        asm("{ .reg .u64 t; cvta.to.shared.u64 t, %1; cvt.u32.u64 %0, t; }"
            : "=r"(u) : "l"((const void*)&win[st][hw][sch * 8]));
        sdst[st] = u;
    }

    // prologue: prefetch pairs 0 and 1 into stages 0 and 1
    if (tid < 64) {
        #pragma unroll
        for (int p = 0; p < 2; p++) {
            int q = 2 * p + hw;
            const __half* src = fb + ((a0 + q) * DET + w0s[q]) * 4 + sch * 8;
            asm volatile("cp.async.ca.shared.global [%0], [%1], 16;\n"
                         :: "r"(sdst[p]), "l"(src) : "memory");
        }
    }
    asm volatile("cp.async.commit_group;\n" ::: "memory");
    asm volatile("cp.async.commit_group;\n" ::: "memory");

    const float jf = (float)(j0 + tx - RAD);
    float xpr[4];
    #pragma unroll
    for (int r = 0; r < 4; r++) xpr[r] = (float)(i0 + ty + 8 * r - RAD);

    float acc[B][4];
    #pragma unroll
    for (int bb = 0; bb < B; bb++)
        #pragma unroll
        for (int r = 0; r < 4; r++) acc[bb][r] = 0.0f;

    const int npairs = APB / 2;          // 15
    int st = 0;
    for (int p = 0; p < npairs; p++) {
        if (p < npairs - 1) {
            asm volatile("cp.async.wait_group 1;\n" ::: "memory");
        } else {
            asm volatile("cp.async.wait_group 0;\n" ::: "memory");
        }
        __syncthreads();   // pair p staged & visible; stage (st+2)%3 free

        {
            int nst = st + 2; if (nst >= PSTG) nst -= PSTG;
            if (p + 2 < npairs && tid < 64) {
                int q = 2 * (p + 2) + hw;
                const __half* src = fb + ((a0 + q) * DET + w0s[q]) * 4
                                  + sch * 8;
                asm volatile("cp.async.ca.shared.global [%0], [%1], 16;\n"
                             :: "r"(sdst[nst]), "l"(src) : "memory");
            }
            asm volatile("cp.async.commit_group;\n" ::: "memory");
        }

        #pragma unroll
        for (int h = 0; h < 2; h++) {
            const int q = 2 * p + h;
            const float c = cs[q];
            const float s = sn[q];
            const int   w0a = w0s[q];
            const float base = fmaf(jf, c, (float)(DET / 2));
            const __half* wp = win[st][h];

            #pragma unroll
            for (int r = 0; r < 4; r++) {
                float pos = fmaf(-xpr[r], s, base);
                int   idx = __float2int_rd(pos);
                float w   = pos - (float)idx;
                // gate: pos in [0,511] <=> float bits <= bits(511.0f)
                int sel = (__float_as_uint(pos) <= GATE_U) ? (idx - w0a)
                                                           : ZSLOT;
                uint2 qa = *reinterpret_cast<const uint2*>(wp + sel * 4);
                uint2 qb = *reinterpret_cast<const uint2*>(wp + sel * 4 + 4);
                __half2 w2 = __float2half2_rn(w);
                __half2 qa01 = *reinterpret_cast<__half2*>(&qa.x);
                __half2 qa23 = *reinterpret_cast<__half2*>(&qa.y);
                __half2 qb01 = *reinterpret_cast<__half2*>(&qb.x);
                __half2 qb23 = *reinterpret_cast<__half2*>(&qb.y);
                __half2 v01 = __hfma2(w2, __hsub2(qb01, qa01), qa01);
                __half2 v23 = __hfma2(w2, __hsub2(qb23, qa23), qa23);
                float2 f01 = __half22float2(v01);
                float2 f23 = __half22float2(v23);
                acc[0][r] += f01.x;
                acc[1][r] += f01.y;
                acc[2][r] += f23.x;
                acc[3][r] += f23.y;
            }
        }

        st++; if (st >= PSTG) st -= PSTG;
    }

    const float scale = PI_F / (2.0f * (float)NTH);
    const int j = j0 + tx;
    if (j < OUT) {
        #pragma unroll
        for (int bb = 0; bb < B; bb++) {
            #pragma unroll
            for (int r = 0; r < 4; r++) {
                int i = i0 + ty + 8 * r;
                if (i < OUT)
                    atomicAdd(&out[(bb * OUT + i) * OUT + j], acc[bb][r] * scale);
            }
        }
    }
}

extern "C" void kernel_launch(void* const* d_in, const int* in_sizes, int n_in,
                              void* d_out, int out_size)
{
    const float* x = (const float*)d_in[0];
    float* out = (float*)d_out;

    filter_kernel<<<dim3(NTH, B), 128>>>(x, out);

    dim3 grid((OUT + 31) / 32, (OUT + 31) / 32, NSPLIT);   // 12 x 12 x 6
    backproj_kernel<<<grid, 256>>>(out);
}